// round 5
// baseline (speedup 1.0000x reference)
#include <cuda_runtime.h>

// Decoder_predict: batched greedy goals-NMS.  B=256, N=4096, T=30, K=6.
// scores = class * centerness, thr^2 = 4.0.
//
// V5: single kernel, one CTA (512 thr, 16 warps) per batch.
//  Phase 1: each warp reduces its 256 candidates (8/thread) to a top-6 by
//           score, shuffle-only, uniform tmax recompute (no divergent
//           refresh). 16 warps * 6 = 96 survivors -> smem.
//  Phase 2: warp 0 runs the 6 greedy NMS rounds over the 96 survivors
//           (3/lane), registers + shuffles only.
//  Phase 3: traj gather with float4 (rows are 240 B = 15 float4).
// Packed key (score_bits<<32)|~idx : scores >= 0 so float bits are
// order-monotone; ~idx = lower-original-index tie-break (matches stable
// argsort); key is never 0 for a real candidate.

#define NMS_B 256
#define NMS_N 4096
#define NMS_T 30
#define NMS_K 6
#define NMS_THR2 4.0f
#define THREADS 512
#define WARPS (THREADS / 32)        // 16
#define SURV (WARPS * NMS_K)        // 96
#define CPT 8                       // candidates per thread

static __device__ __forceinline__ unsigned long long pack_key(float s, unsigned idx) {
    return ((unsigned long long)__float_as_uint(s) << 32) | (unsigned)(~idx);
}

__global__ __launch_bounds__(THREADS, 2)
void nms_goals_kernel(const float* __restrict__ coord,   // [B,1,N,2]
                      const float* __restrict__ cls,     // [B,1,N]
                      const float* __restrict__ traj,    // [B,1,N,T,2]
                      const float* __restrict__ cent,    // [B,1,N]
                      float* __restrict__ out)
{
    const int b    = blockIdx.x;
    const int tid  = threadIdx.x;
    const int wid  = tid >> 5;
    const int lane = tid & 31;

    const float4* c4 = (const float4*)(coord + (size_t)b * NMS_N * 2);
    const float2* s2 = (const float2*)(cls   + (size_t)b * NMS_N);
    const float2* e2 = (const float2*)(cent  + (size_t)b * NMS_N);

    // 8 candidates per thread: pair k covers global indices
    // 2*(tid + k*512), 2*(tid + k*512)+1  (fully coalesced wide loads).
    float x[CPT], y[CPT];
    unsigned long long pk[CPT];
    {
        float4 cv[4]; float2 sv[4], ev[4];
#pragma unroll
        for (int k = 0; k < 4; k++) cv[k] = c4[tid + k * THREADS];
#pragma unroll
        for (int k = 0; k < 4; k++) sv[k] = s2[tid + k * THREADS];
#pragma unroll
        for (int k = 0; k < 4; k++) ev[k] = e2[tid + k * THREADS];
#pragma unroll
        for (int k = 0; k < 4; k++) {
            const unsigned i0 = 2u * (unsigned)(tid + k * THREADS);
            x[2*k]   = cv[k].x;  y[2*k]   = cv[k].y;
            x[2*k+1] = cv[k].z;  y[2*k+1] = cv[k].w;
            pk[2*k]   = pack_key(sv[k].x * ev[k].x, i0);
            pk[2*k+1] = pack_key(sv[k].y * ev[k].y, i0 + 1u);
        }
    }

    __shared__ float4 surv[SURV];               // x, y, score, ~idx bits
    __shared__ float  sel_x[NMS_K], sel_y[NMS_K], sel_s[NMS_K];
    __shared__ int    sel_i[NMS_K];

    // ---- Phase 1: per-warp top-6 by score. ----
#pragma unroll
    for (int r = 0; r < NMS_K; r++) {
        // Uniform (all-lane) per-thread max, then warp max.
        unsigned long long tmax = pk[0];
#pragma unroll
        for (int j = 1; j < CPT; j++) tmax = max(tmax, pk[j]);
        unsigned long long m = tmax;
#pragma unroll
        for (int off = 16; off > 0; off >>= 1)
            m = max(m, __shfl_xor_sync(0xFFFFFFFFu, m, off));

        const bool mine = (tmax == m);        // keys unique -> exactly one lane
        if (mine) {
            float wx = 0.f, wy = 0.f;
#pragma unroll
            for (int j = 0; j < CPT; j++)
                if (pk[j] == m) { wx = x[j]; wy = y[j]; pk[j] = 0ULL; }
            surv[wid * NMS_K + r] = make_float4(
                wx, wy,
                __uint_as_float((unsigned)(m >> 32)),
                __uint_as_float((unsigned)(m & 0xFFFFFFFFu)));   // ~idx bits
        }
    }
    __syncthreads();

    // ---- Phase 2: warp 0 greedy NMS over 96 survivors (3 per lane). ----
    if (wid == 0) {
        float  vx[3], vy[3];
        unsigned long long vp[3];
#pragma unroll
        for (int h = 0; h < 3; h++) {
            const float4 v = surv[lane + 32 * h];
            vx[h] = v.x;  vy[h] = v.y;
            vp[h] = ((unsigned long long)__float_as_uint(v.z) << 32)
                  | (unsigned)__float_as_uint(v.w);
        }
#pragma unroll
        for (int r = 0; r < NMS_K; r++) {
            unsigned long long m = max(max(vp[0], vp[1]), vp[2]);
#pragma unroll
            for (int off = 16; off > 0; off >>= 1)
                m = max(m, __shfl_xor_sync(0xFFFFFFFFu, m, off));

            if (m == 0ULL) {
                if (lane == 0) {
                    sel_i[r] = -1; sel_s[r] = 0.0f;
                    sel_x[r] = 0.0f; sel_y[r] = 0.0f;
                }
            } else {
                int hm = 0; bool mine = false;
#pragma unroll
                for (int h = 0; h < 3; h++)
                    if (vp[h] == m) { hm = h; mine = true; }
                const unsigned bal = __ballot_sync(0xFFFFFFFFu, mine);
                const int wl = __ffs(bal) - 1;
                float fx = vx[0], fy = vy[0];
#pragma unroll
                for (int h = 1; h < 3; h++)
                    if (h == hm) { fx = vx[h]; fy = vy[h]; }
                const float px = __shfl_sync(0xFFFFFFFFu, fx, wl);
                const float py = __shfl_sync(0xFFFFFFFFu, fy, wl);
                if (lane == wl) {
                    sel_x[r] = px;  sel_y[r] = py;
                    sel_s[r] = __uint_as_float((unsigned)(m >> 32));
                    sel_i[r] = (int)(~(unsigned)(m & 0xFFFFFFFFu));
                }
                // Suppress survivors within thr (incl. the winner itself).
#pragma unroll
                for (int h = 0; h < 3; h++) {
                    const float dx = vx[h] - px;
                    const float dy = vy[h] - py;
                    if (dx * dx + dy * dy < NMS_THR2) vp[h] = 0ULL;
                }
            }
        }
    }
    __syncthreads();

    // ---- Phase 3: outputs. pred_trajs [B,K,T,2] | probs [B,K] | goals [B,K,2]
    float* out_traj = out;
    float* out_prob = out + (size_t)NMS_B * NMS_K * NMS_T * 2;
    float* out_goal = out_prob + (size_t)NMS_B * NMS_K;

    if (tid < NMS_K) {
        const int  k     = tid;
        const bool valid = (sel_i[k] >= 0);
        out_prob[(size_t)b * NMS_K + k]           = valid ? sel_s[k] : sel_s[0];
        out_goal[((size_t)b * NMS_K + k) * 2 + 0] = valid ? sel_x[k] : 0.0f;
        out_goal[((size_t)b * NMS_K + k) * 2 + 1] = valid ? sel_y[k] : 0.0f;
    }

    // Traj gather: 6 rows * 15 float4 = 90 float4 per batch.
    if (tid < NMS_K * 15) {
        const int k = tid / 15;
        const int q = tid % 15;
        const int src = (sel_i[k] >= 0) ? sel_i[k] : sel_i[0];
        ((float4*)out_traj)[((size_t)b * NMS_K + k) * 15 + q] =
            ((const float4*)traj)[((size_t)b * NMS_N + src) * 15 + q];
    }
}

extern "C" void kernel_launch(void* const* d_in, const int* in_sizes, int n_in,
                              void* d_out, int out_size) {
    const float* coord = (const float*)d_in[0];  // outputs_coord     [B,1,N,2]
    const float* cls   = (const float*)d_in[1];  // outputs_class     [B,1,N]
    const float* traj  = (const float*)d_in[2];  // outputs_traj      [B,1,N,T,2]
    const float* cent  = (const float*)d_in[3];  // outputs_centerness[B,1,N]
    float* out = (float*)d_out;

    nms_goals_kernel<<<NMS_B, THREADS>>>(coord, cls, traj, cent, out);
}